// round 2
// baseline (speedup 1.0000x reference)
#include <cuda_runtime.h>

#define BDIM 8
#define NPTS 4096
#define DDIM 64
#define KNN 16
#define STRIPS 4
#define STRIP_LEN (NPTS / STRIPS)       // 1024
#define QPB 128                          // queries per phase-1 block
#define P1_THREADS (QPB * STRIPS)        // 512
#define P1_BLOCKS (BDIM * NPTS / QPB)    // 256
#define CHUNK 256
#define DEPTH 64

typedef unsigned long long ull;

// Device-global scratch (no allocations allowed).
__device__ ull g_buf[(size_t)P1_BLOCKS * P1_THREADS * DEPTH];  // 64 MB
__device__ int g_knn[BDIM * NPTS * KNN];                       // 2 MB

// Sorted-ascending top-16 insert, strict lexicographic (d, idx) ==
// jnp stable-argsort order. Fully predicated, branch-free.
__device__ __forceinline__ void insert16(float (&dist)[KNN], int (&idx)[KNN],
                                          float cd, int cm) {
#pragma unroll
    for (int j = 0; j < KNN; j++) {
        bool lt = (cd < dist[j]) || ((cd == dist[j]) && (cm < idx[j]));
        float od = dist[j]; int oi = idx[j];
        dist[j] = lt ? cd : od;
        idx[j]  = lt ? cm : oi;
        cd = lt ? od : cd;
        cm = lt ? oi : cm;
    }
}

__device__ __forceinline__ float pdist(float4 q, float4 c) {
    float t = q.x * c.x;
    t = fmaf(q.y, c.y, t);
    t = fmaf(q.z, c.z, t);
    return fmaf(-2.0f, t, q.w + c.w);   // identical fp order to round-1 pass
}

// ---------------- Phase 1: fused distance + top-16, strip-parallel ----------
// Block: 512 threads = 128 queries x 4 candidate strips. Point cloud cached
// in smem; per-strip top-16 in regs; strips merged through smem at the end.
extern "C" __global__ void __launch_bounds__(P1_THREADS)
knn_kernel(const float* __restrict__ xyz)
{
    extern __shared__ float4 cand[];   // [NPTS] = 64 KB, reused as merge area
    int b  = blockIdx.x >> 5;          // 32 blocks per batch
    int n0 = (blockIdx.x & 31) * QPB;
    const float* xb = xyz + (size_t)b * NPTS * 3;

    for (int m = threadIdx.x; m < NPTS; m += P1_THREADS) {
        float mx = xb[3*m], my = xb[3*m+1], mz = xb[3*m+2];
        float s = mx*mx; s = fmaf(my, my, s); s = fmaf(mz, mz, s);
        cand[m] = make_float4(mx, my, mz, s);
    }
    __syncthreads();

    int lq = threadIdx.x & (QPB - 1);
    int s  = threadIdx.x >> 7;          // strip id 0..3
    int n  = n0 + lq;
    float4 q = cand[n];

    float dist[KNN]; int idx[KNN];
#pragma unroll
    for (int j = 0; j < KNN; j++) { dist[j] = 3.0e38f; idx[j] = 0x7fffffff; }

    int m0 = s * STRIP_LEN;

    // Seed: 16 unconditional inserts (convergent, fills the list).
#pragma unroll 1
    for (int m = m0; m < m0 + KNN; m++)
        insert16(dist, idx, pdist(q, cand[m]), m);
    float thr = dist[KNN - 1];

    ull* buf = g_buf + (size_t)(blockIdx.x * P1_THREADS + threadIdx.x) * DEPTH;

    // Main: 256-candidate chunks, deferred buffered insertion, convergent drain.
    for (int base = m0 + KNN; base < m0 + STRIP_LEN; base += CHUNK) {
        int end = base + CHUNK; if (end > m0 + STRIP_LEN) end = m0 + STRIP_LEN;
        int cnt = 0;
#pragma unroll 4
        for (int m = base; m < end; m++) {
            float d = pdist(q, cand[m]);
            if (d < thr) {
                if (cnt < DEPTH) {
                    buf[cnt++] = (ull)__float_as_uint(d) | ((ull)(unsigned)m << 32);
                } else {                       // overflow safety path (rare)
                    insert16(dist, idx, d, m);
                    thr = dist[KNN - 1];
                }
            }
        }
        int cm = cnt;
#pragma unroll
        for (int o = 16; o > 0; o >>= 1) {
            int t2 = __shfl_xor_sync(0xffffffffu, cm, o);
            cm = cm > t2 ? cm : t2;
        }
        for (int j = 0; j < cm; j++) {
            float cd = 3.0e38f; int ci = 0x7fffffff;
            if (j < cnt) {
                ull pk = buf[j];
                cd = __uint_as_float((unsigned)pk);
                ci = (int)(pk >> 32);
            }
            insert16(dist, idx, cd, ci);
        }
        thr = dist[KNN - 1];
    }

    // Merge strips through smem (cand no longer needed).
    __syncthreads();
    ull* pairs = (ull*)cand;
#pragma unroll
    for (int j = 0; j < KNN; j++)
        pairs[threadIdx.x * KNN + j] =
            (ull)__float_as_uint(dist[j]) | ((ull)(unsigned)idx[j] << 32);
    __syncthreads();

    if (threadIdx.x < QPB) {
#pragma unroll 1
        for (int s2 = 1; s2 < STRIPS; s2++) {
#pragma unroll
            for (int j = 0; j < KNN; j++) {
                ull pk = pairs[(threadIdx.x + QPB * s2) * KNN + j];
                insert16(dist, idx, __uint_as_float((unsigned)pk), (int)(pk >> 32));
            }
        }
        int4* kp = (int4*)(g_knn + ((size_t)b * NPTS + n) * KNN);
        kp[0] = make_int4(idx[0],  idx[1],  idx[2],  idx[3]);
        kp[1] = make_int4(idx[4],  idx[5],  idx[6],  idx[7]);
        kp[2] = make_int4(idx[8],  idx[9],  idx[10], idx[11]);
        kp[3] = make_int4(idx[12], idx[13], idx[14], idx[15]);
    }
}

// ---------------- Phase 2: MLP + staged transpose-add epilogue --------------
// Block: 128 threads = 16 n x 8 k points; grid = B * 256 ntiles * 2 khalves.
// pos_enc rows staged in swizzled smem, then coalesced x-add + store.
#define MLP_SMEM_FLOATS (DDIM*DDIM + 4*DDIM + DDIM + 128*DDIM)

extern "C" __global__ void __launch_bounds__(128, 4)
mlp_kernel(const float* __restrict__ xyz, const float* __restrict__ x,
           const float* __restrict__ W1, const float* __restrict__ b1,
           const float* __restrict__ W2, const float* __restrict__ b2,
           float* __restrict__ out)
{
    extern __shared__ float sm[];
    float*  W2s = sm;                                // 4096
    float4* W1p = (float4*)(sm + DDIM*DDIM);         // 64 float4
    float*  b2s = sm + DDIM*DDIM + 4*DDIM;           // 64
    float*  stg = sm + DDIM*DDIM + 4*DDIM + DDIM;    // 128 x 64 staging

    int tid = threadIdx.x;
    for (int i = tid; i < DDIM*DDIM; i += 128) W2s[i] = W2[i];
    if (tid < DDIM) {
        W1p[tid] = make_float4(W1[tid], W1[DDIM + tid], W1[2*DDIM + tid], b1[tid]);
        b2s[tid] = b2[tid];
    }
    __syncthreads();

    int kh = blockIdx.x & 1;
    int nt = (blockIdx.x >> 1) & 255;
    int b  = blockIdx.x >> 9;
    int j  = tid & 15;                 // n within tile
    int kl = tid >> 4;                 // 0..7
    int n  = nt * 16 + j;
    int k  = kh * 8 + kl;

    int m = g_knn[(((size_t)b * NPTS + n) << 4) + k];
    const float* xb = xyz + (size_t)b * NPTS * 3;
    float dx = xb[3*n]   - xb[3*m];
    float dy = xb[3*n+1] - xb[3*m+1];
    float dz = xb[3*n+2] - xb[3*m+2];

    ull acc[DDIM / 2];
    const ull* b2p = (const ull*)b2s;
#pragma unroll
    for (int e = 0; e < DDIM / 2; e++) acc[e] = b2p[e];

#pragma unroll 4
    for (int d = 0; d < DDIM; d++) {
        float4 w1 = W1p[d];
        float h = w1.w;
        h = fmaf(dx, w1.x, h);
        h = fmaf(dy, w1.y, h);
        h = fmaf(dz, w1.z, h);
        h = fmaxf(h, 0.0f);
        if (__all_sync(0xffffffffu, h == 0.0f)) continue;  // dead ReLU row skip
        ull h2;
        asm("mov.b64 %0, {%1, %1};" : "=l"(h2) : "r"(__float_as_int(h)));
        const ulonglong2* w = (const ulonglong2*)(W2s + (d << 6));
#pragma unroll
        for (int e = 0; e < 16; e++) {
            ulonglong2 wv = w[e];   // LDS.128 broadcast
            asm("fma.rn.f32x2 %0, %1, %2, %0;" : "+l"(acc[2*e])   : "l"(h2), "l"(wv.x));
            asm("fma.rn.f32x2 %0, %1, %2, %0;" : "+l"(acc[2*e+1]) : "l"(h2), "l"(wv.y));
        }
    }

    // Stage row (XOR-swizzled float4 columns to dodge bank conflicts).
    ulonglong2* st2 = (ulonglong2*)stg;
#pragma unroll
    for (int e = 0; e < 16; e++) {
        ulonglong2 v; v.x = acc[2*e]; v.y = acc[2*e+1];
        st2[tid * 16 + (e ^ (tid & 15))] = v;
    }
    __syncthreads();

    // Coalesced flush: out[b,k,n,:] = x[b,k,n,:] + stg (pos_enc).
    const ulonglong2* xg = (const ulonglong2*)x;
    ulonglong2*       og = (ulonglong2*)out;
#pragma unroll
    for (int i = 0; i < 16; i++) {
        int f    = tid + 128 * i;
        int c4   = f & 15;
        int row  = f >> 4;            // source thread id
        int kk   = kh * 8 + (row >> 4);
        int jj   = row & 15;
        ulonglong2 pv = st2[row * 16 + (c4 ^ (row & 15))];
        size_t gi = ((((size_t)b * KNN + kk) * NPTS) + nt * 16 + jj) * 16 + c4;
        ulonglong2 xv = xg[gi];
        ulonglong2 r;
        asm("add.rn.f32x2 %0, %1, %2;" : "=l"(r.x) : "l"(pv.x), "l"(xv.x));
        asm("add.rn.f32x2 %0, %1, %2;" : "=l"(r.y) : "l"(pv.y), "l"(xv.y));
        og[gi] = r;
    }
}

extern "C" void kernel_launch(void* const* d_in, const int* in_sizes, int n_in,
                              void* d_out, int out_size) {
    const float* xyz = (const float*)d_in[0];
    const float* x   = (const float*)d_in[1];
    const float* W1  = (const float*)d_in[2];
    const float* b1  = (const float*)d_in[3];
    const float* W2  = (const float*)d_in[4];
    const float* b2  = (const float*)d_in[5];
    float* out = (float*)d_out;

    cudaFuncSetAttribute(knn_kernel, cudaFuncAttributeMaxDynamicSharedMemorySize,
                         NPTS * (int)sizeof(float4));
    cudaFuncSetAttribute(mlp_kernel, cudaFuncAttributeMaxDynamicSharedMemorySize,
                         MLP_SMEM_FLOATS * (int)sizeof(float));

    knn_kernel<<<P1_BLOCKS, P1_THREADS, NPTS * sizeof(float4)>>>(xyz);
    mlp_kernel<<<BDIM * 256 * 2, 128, MLP_SMEM_FLOATS * sizeof(float)>>>(
        xyz, x, W1, b1, W2, b2, out);
}

// round 4
// speedup vs baseline: 1.5678x; 1.5678x over previous
#include <cuda_runtime.h>

#define BDIM 8
#define NPTS 4096
#define DDIM 64
#define KNN 16
#define QPB 128                          // queries per phase-1 block
#define P1T 256                          // threads per phase-1 block
#define TILE 512                         // candidates per smem tile
#define NT (NPTS / TILE)                 // 8 tiles
#define HALF 256                         // candidates per strip per tile
#define DEPTH 32                         // smem buffer slots per thread
#define SEED 64

typedef unsigned long long ull;

__device__ int g_knn[BDIM * NPTS * KNN];   // 2 MB knn indices

// key = (sortable_bits(d) << 32) | idx. Monotone float->uint transform makes
// unsigned compare == exact lexicographic (d, idx) == jnp stable argsort,
// including (pathological) negative d from rounding.
__device__ __forceinline__ ull packK(float d, int m) {
    unsigned ub = __float_as_uint(d);
    ub ^= ((unsigned)((int)ub >> 31)) | 0x80000000u;
    return ((ull)ub << 32) | (unsigned)m;
}
__device__ __forceinline__ float thrOf(ull k) {      // inverse transform of hi
    unsigned h = (unsigned)(k >> 32);
    unsigned bits = (h & 0x80000000u) ? (h ^ 0x80000000u) : ~h;
    return __uint_as_float(bits);
}

__device__ __forceinline__ void insertK(ull (&key)[KNN], ull ck) {
#pragma unroll
    for (int j = 0; j < KNN; j++) {
        bool lt = ck < key[j];
        ull o = key[j];
        key[j] = lt ? ck : o;
        ck     = lt ? o  : ck;
    }
}

__device__ __forceinline__ float pdist(float4 q, float4 c) {
    float t = q.x * c.x;
    t = fmaf(q.y, c.y, t);
    t = fmaf(q.z, c.z, t);
    return fmaf(-2.0f, t, q.w + c.w);   // identical fp order to passing rounds
}

// ---------------- Phase 1: fused distance + exact top-16 --------------------
// 256 threads = 128 queries x 2 intra-tile strips. Candidates streamed through
// smem in 512-pt tiles; accepts buffered in SMEM [DEPTH][P1T] (conflict-free),
// drained convergently with warp-max trip count. No local/global scratch.
#define KNN_SMEM (TILE*16 + TILE*12 + DEPTH*P1T*8)   // 8K + 6K + 64K

extern "C" __global__ void __launch_bounds__(P1T)
knn_kernel(const float* __restrict__ xyz)
{
    extern __shared__ char smem_raw[];
    float4* cand = (float4*)smem_raw;                          // [TILE]
    float*  raw  = (float*)(smem_raw + TILE * 16);             // [TILE*3]
    ull*    buf  = (ull*)(smem_raw + TILE * 16 + TILE * 12);   // [DEPTH][P1T]

    int b  = blockIdx.x >> 5;          // 32 blocks per batch
    int n0 = (blockIdx.x & 31) * QPB;
    const float* xb = xyz + (size_t)b * NPTS * 3;

    int lq = threadIdx.x & (QPB - 1);
    int s  = threadIdx.x >> 7;          // strip 0/1 (warp-uniform)
    int n  = n0 + lq;

    float qx = xb[3*n], qy = xb[3*n+1], qz = xb[3*n+2];
    float qw = qx*qx; qw = fmaf(qy, qy, qw); qw = fmaf(qz, qz, qw);
    float4 q = make_float4(qx, qy, qz, qw);

    ull key[KNN];
#pragma unroll
    for (int j = 0; j < KNN; j++) key[j] = ~0ull;   // inert max sentinel

#pragma unroll 1
    for (int t = 0; t < NT; t++) {
        int p0 = t * TILE;
        __syncthreads();                 // previous tile fully consumed
        for (int i = threadIdx.x; i < TILE * 3; i += P1T)
            raw[i] = xb[p0 * 3 + i];     // coalesced
        __syncthreads();
        for (int p = threadIdx.x; p < TILE; p += P1T) {
            float cx = raw[3*p], cy = raw[3*p+1], cz = raw[3*p+2];
            float cw = cx*cx; cw = fmaf(cy, cy, cw); cw = fmaf(cz, cz, cw);
            cand[p] = make_float4(cx, cy, cz, cw);
        }
        __syncthreads();

        int c0 = s * HALF;               // this strip's half of the tile
        int m0 = p0 + c0;
        int start = 0;

        if (t == 0) {                    // seed: direct guarded inserts
#pragma unroll 1
            for (int i = 0; i < SEED; i++) {
                ull ck = packK(pdist(q, cand[c0 + i]), m0 + i);
                if (ck < key[KNN - 1]) insertK(key, ck);
            }
            start = SEED;
        }

        float thr = thrOf(key[KNN - 1]);
        int cnt = 0;
#pragma unroll 4
        for (int i = start; i < HALF; i++) {
            float d = pdist(q, cand[c0 + i]);
            if (d <= thr) {              // <= keeps tie exactness
                ull ck = packK(d, m0 + i);
                if (cnt < DEPTH) { buf[cnt * P1T + threadIdx.x] = ck; cnt++; }
                else              insertK(key, ck);   // rare overflow path
            }
        }
        int cm = cnt;                    // convergent drain trip count
#pragma unroll
        for (int o = 16; o > 0; o >>= 1) {
            int t2 = __shfl_xor_sync(0xffffffffu, cm, o);
            cm = cm > t2 ? cm : t2;
        }
#pragma unroll 2
        for (int j = 0; j < cm; j++) {
            ull ck = (j < cnt) ? buf[j * P1T + threadIdx.x] : ~0ull;
            insertK(key, ck);
        }
    }

    // Merge the two strips through smem.
    __syncthreads();
    ull* pairs = (ull*)smem_raw;         // 16 KB, cand/raw/buf dead now
    if (s == 1) {
#pragma unroll
        for (int j = 0; j < KNN; j++) pairs[lq * KNN + j] = key[j];
    }
    __syncthreads();

    if (s == 0) {
#pragma unroll
        for (int j = 0; j < KNN; j++) insertK(key, pairs[lq * KNN + j]);

        int4* kp = (int4*)(g_knn + ((size_t)b * NPTS + n) * KNN);
        kp[0] = make_int4((int)(unsigned)key[0],  (int)(unsigned)key[1],
                          (int)(unsigned)key[2],  (int)(unsigned)key[3]);
        kp[1] = make_int4((int)(unsigned)key[4],  (int)(unsigned)key[5],
                          (int)(unsigned)key[6],  (int)(unsigned)key[7]);
        kp[2] = make_int4((int)(unsigned)key[8],  (int)(unsigned)key[9],
                          (int)(unsigned)key[10], (int)(unsigned)key[11]);
        kp[3] = make_int4((int)(unsigned)key[12], (int)(unsigned)key[13],
                          (int)(unsigned)key[14], (int)(unsigned)key[15]);
    }
}

// ---------------- Phase 2: MLP + staged transpose-add epilogue --------------
// (unchanged from round 2: 123.5 us measured)
#define MLP_SMEM_FLOATS (DDIM*DDIM + 4*DDIM + DDIM + 128*DDIM)

extern "C" __global__ void __launch_bounds__(128, 4)
mlp_kernel(const float* __restrict__ xyz, const float* __restrict__ x,
           const float* __restrict__ W1, const float* __restrict__ b1,
           const float* __restrict__ W2, const float* __restrict__ b2,
           float* __restrict__ out)
{
    extern __shared__ float sm[];
    float*  W2s = sm;                                // 4096
    float4* W1p = (float4*)(sm + DDIM*DDIM);         // 64 float4
    float*  b2s = sm + DDIM*DDIM + 4*DDIM;           // 64
    float*  stg = sm + DDIM*DDIM + 4*DDIM + DDIM;    // 128 x 64 staging

    int tid = threadIdx.x;
    for (int i = tid; i < DDIM*DDIM; i += 128) W2s[i] = W2[i];
    if (tid < DDIM) {
        W1p[tid] = make_float4(W1[tid], W1[DDIM + tid], W1[2*DDIM + tid], b1[tid]);
        b2s[tid] = b2[tid];
    }
    __syncthreads();

    int kh = blockIdx.x & 1;
    int nt = (blockIdx.x >> 1) & 255;
    int b  = blockIdx.x >> 9;
    int j  = tid & 15;                 // n within tile
    int kl = tid >> 4;                 // 0..7
    int n  = nt * 16 + j;

    int m = g_knn[(((size_t)b * NPTS + n) << 4) + kh * 8 + kl];
    const float* xb = xyz + (size_t)b * NPTS * 3;
    float dx = xb[3*n]   - xb[3*m];
    float dy = xb[3*n+1] - xb[3*m+1];
    float dz = xb[3*n+2] - xb[3*m+2];

    typedef unsigned long long ull_t;
    ull_t acc[DDIM / 2];
    const ull_t* b2p = (const ull_t*)b2s;
#pragma unroll
    for (int e = 0; e < DDIM / 2; e++) acc[e] = b2p[e];

#pragma unroll 4
    for (int d = 0; d < DDIM; d++) {
        float4 w1 = W1p[d];
        float h = w1.w;
        h = fmaf(dx, w1.x, h);
        h = fmaf(dy, w1.y, h);
        h = fmaf(dz, w1.z, h);
        h = fmaxf(h, 0.0f);
        if (__all_sync(0xffffffffu, h == 0.0f)) continue;  // dead ReLU row skip
        ull_t h2;
        asm("mov.b64 %0, {%1, %1};" : "=l"(h2) : "r"(__float_as_int(h)));
        const ulonglong2* w = (const ulonglong2*)(W2s + (d << 6));
#pragma unroll
        for (int e = 0; e < 16; e++) {
            ulonglong2 wv = w[e];   // LDS.128 broadcast
            asm("fma.rn.f32x2 %0, %1, %2, %0;" : "+l"(acc[2*e])   : "l"(h2), "l"(wv.x));
            asm("fma.rn.f32x2 %0, %1, %2, %0;" : "+l"(acc[2*e+1]) : "l"(h2), "l"(wv.y));
        }
    }

    // Stage row (XOR-swizzled float4 columns to dodge bank conflicts).
    ulonglong2* st2 = (ulonglong2*)stg;
#pragma unroll
    for (int e = 0; e < 16; e++) {
        ulonglong2 v; v.x = acc[2*e]; v.y = acc[2*e+1];
        st2[tid * 16 + (e ^ (tid & 15))] = v;
    }
    __syncthreads();

    // Coalesced flush: out[b,k,n,:] = x[b,k,n,:] + stg (pos_enc).
    const ulonglong2* xg = (const ulonglong2*)x;
    ulonglong2*       og = (ulonglong2*)out;
#pragma unroll
    for (int i = 0; i < 16; i++) {
        int f    = tid + 128 * i;
        int c4   = f & 15;
        int row  = f >> 4;            // source thread id
        int kk   = kh * 8 + (row >> 4);
        int jj   = row & 15;
        ulonglong2 pv = st2[row * 16 + (c4 ^ (row & 15))];
        size_t gi = ((((size_t)b * KNN + kk) * NPTS) + nt * 16 + jj) * 16 + c4;
        ulonglong2 xv = xg[gi];
        ulonglong2 r;
        asm("add.rn.f32x2 %0, %1, %2;" : "=l"(r.x) : "l"(pv.x), "l"(xv.x));
        asm("add.rn.f32x2 %0, %1, %2;" : "=l"(r.y) : "l"(pv.y), "l"(xv.y));
        og[gi] = r;
    }
}

extern "C" void kernel_launch(void* const* d_in, const int* in_sizes, int n_in,
                              void* d_out, int out_size) {
    const float* xyz = (const float*)d_in[0];
    const float* x   = (const float*)d_in[1];
    const float* W1  = (const float*)d_in[2];
    const float* b1  = (const float*)d_in[3];
    const float* W2  = (const float*)d_in[4];
    const float* b2  = (const float*)d_in[5];
    float* out = (float*)d_out;

    cudaFuncSetAttribute(knn_kernel, cudaFuncAttributeMaxDynamicSharedMemorySize,
                         KNN_SMEM);
    cudaFuncSetAttribute(mlp_kernel, cudaFuncAttributeMaxDynamicSharedMemorySize,
                         MLP_SMEM_FLOATS * (int)sizeof(float));

    knn_kernel<<<BDIM * NPTS / QPB, P1T, KNN_SMEM>>>(xyz);
    mlp_kernel<<<BDIM * 256 * 2, 128, MLP_SMEM_FLOATS * sizeof(float)>>>(
        xyz, x, W1, b1, W2, b2, out);
}